// round 13
// baseline (speedup 1.0000x reference)
#include <cuda_runtime.h>
#include <cuda_fp16.h>
#include <stdint.h>

#define BATCH  2
#define SEQ    2048
#define DMODEL 1024
#define NHEAD  16
#define HDIM   64
#define D3     3072

// Scratch: Q/K/V natural [B,H,S,hd] floats; vals [B,S,D] floats.
__device__ __align__(16) float g_Q   [BATCH * NHEAD * SEQ * HDIM];
__device__ __align__(16) float g_K   [BATCH * NHEAD * SEQ * HDIM];
__device__ __align__(16) float g_V   [BATCH * NHEAD * SEQ * HDIM];
__device__ __align__(16) float g_vals[BATCH * SEQ * DMODEL];
// Pre-split planes (uint32 = half2 word; low half = smaller index):
//  K planes: [B*H*S][32]   pairs along d  (hi+lo)
//  V plane : [B*H*S/2][64] pairs along s  (hi only — lo term dropped, see R13 notes)
__device__ __align__(16) uint32_t g_Kph[BATCH * NHEAD * SEQ * 32];
__device__ __align__(16) uint32_t g_Kpl[BATCH * NHEAD * SEQ * 32];
__device__ __align__(16) uint32_t g_Vph[BATCH * NHEAD * (SEQ / 2) * 64];

// ---- fp16 split helpers ----------------------------------------------------
__device__ __forceinline__ void h2split(float a, float b, uint32_t& hi, uint32_t& lo) {
    __half2 h = __floats2half2_rn(a, b);
    float2 f = __half22float2(h);
    __half2 l = __floats2half2_rn(a - f.x, b - f.y);
    hi = *(uint32_t*)&h;
    lo = *(uint32_t*)&l;
}
__device__ __forceinline__ uint32_t h2hi(float a, float b) {
    __half2 h = __floats2half2_rn(a, b);
    return *(uint32_t*)&h;
}
__device__ __forceinline__ void mma16(float* c, const uint32_t* a, const uint32_t* b) {
    asm volatile(
        "mma.sync.aligned.m16n8k16.row.col.f32.f16.f16.f32 "
        "{%0,%1,%2,%3},{%4,%5,%6,%7},{%8,%9},{%0,%1,%2,%3};"
        : "+f"(c[0]), "+f"(c[1]), "+f"(c[2]), "+f"(c[3])
        : "r"(a[0]), "r"(a[1]), "r"(a[2]), "r"(a[3]), "r"(b[0]), "r"(b[1]));
}

// ---------------------------------------------------------------------------
// Prep kernels: reference device globals DIRECTLY (no host-passed symbols).
// ---------------------------------------------------------------------------
#define KQUADS (BATCH * NHEAD * SEQ * 32 / 4)
__global__ void split_k_kernel() {
    int i = blockIdx.x * blockDim.x + threadIdx.x;
    if (i >= KQUADS) return;
    int w0 = i * 4;
    float4 f0 = *(const float4*)&g_K[2 * w0];
    float4 f1 = *(const float4*)&g_K[2 * w0 + 4];
    uint32_t h0, l0, h1, l1, h2, l2, h3, l3;
    h2split(f0.x, f0.y, h0, l0); h2split(f0.z, f0.w, h1, l1);
    h2split(f1.x, f1.y, h2, l2); h2split(f1.z, f1.w, h3, l3);
    *(uint4*)&g_Kph[w0] = make_uint4(h0, h1, h2, h3);
    *(uint4*)&g_Kpl[w0] = make_uint4(l0, l1, l2, l3);
}

#define VPAIRS (BATCH * NHEAD * SEQ / 2)
__global__ void split_v_kernel() {
    int i = blockIdx.x * blockDim.x + threadIdx.x;   // p*16 + q
    int p = i >> 4, q4 = (i & 15) * 4;
    if (p >= VPAIRS) return;
    float4 a = *(const float4*)&g_V[(size_t)(2 * p) * HDIM + q4];
    float4 b = *(const float4*)&g_V[(size_t)(2 * p + 1) * HDIM + q4];
    size_t o = (size_t)p * HDIM + q4;
    *(uint4*)&g_Vph[o] = make_uint4(h2hi(a.x, b.x), h2hi(a.y, b.y),
                                    h2hi(a.z, b.z), h2hi(a.w, b.w));
}

// ---------------------------------------------------------------------------
// GEMM (R6-proven): C[128x128], BK=16, 8 warps (4M x 2N), warp 32x64.
// fp16 hi/lo planes in smem, double-buffered, split at staging.
// ---------------------------------------------------------------------------
#define GA_W   12
#define GB_W   136
#define GA_SZ  (128 * GA_W)
#define GB_SZ  (8 * GB_W)
#define GEMM_WORDS (4 * GA_SZ + 4 * GB_SZ)
#define GEMM_BYTES (GEMM_WORDS * 4)

template <int LDB, bool QKV>
__device__ __forceinline__ void gemm_body(const float* __restrict__ A,
                                          const float* __restrict__ B,
                                          const float* __restrict__ bias,
                                          float* __restrict__ outp,
                                          int m0, int n0, int K) {
    extern __shared__ uint32_t smw[];
    uint32_t* Ah = smw;
    uint32_t* Al = Ah + 2 * GA_SZ;
    uint32_t* Bh = Al + 2 * GA_SZ;
    uint32_t* Bl = Bh + 2 * GB_SZ;

    const int tid = threadIdx.x;
    const int lane = tid & 31, warp = tid >> 5;
    const int g = lane >> 2, t = lane & 3;
    const int wm = (warp & 3) * 32, wn = (warp >> 2) * 64;

    float c[2][8][4];
#pragma unroll
    for (int mi = 0; mi < 2; mi++)
#pragma unroll
        for (int jj = 0; jj < 8; jj++)
#pragma unroll
            for (int e = 0; e < 4; e++) c[mi][jj][e] = 0.f;

    const int am = tid >> 1, ah = tid & 1;
    const int bp = tid >> 5, bc = (tid & 31) * 4;

    float4 ra0, ra1, rb0, rb1;
    ra0 = *(const float4*)&A[(size_t)(m0 + am) * K + 8 * ah];
    ra1 = *(const float4*)&A[(size_t)(m0 + am) * K + 8 * ah + 4];
    rb0 = *(const float4*)&B[(size_t)(2 * bp) * LDB + n0 + bc];
    rb1 = *(const float4*)&B[(size_t)(2 * bp + 1) * LDB + n0 + bc];

#define GEMM_STAGE(buf)                                                        \
    {                                                                          \
        uint32_t w0h, w0l, w1h, w1l, w2h, w2l, w3h, w3l;                       \
        h2split(ra0.x, ra0.y, w0h, w0l); h2split(ra0.z, ra0.w, w1h, w1l);      \
        h2split(ra1.x, ra1.y, w2h, w2l); h2split(ra1.z, ra1.w, w3h, w3l);      \
        *(uint4*)&Ah[(buf) * GA_SZ + am * GA_W + 4 * ah] =                     \
            make_uint4(w0h, w1h, w2h, w3h);                                    \
        *(uint4*)&Al[(buf) * GA_SZ + am * GA_W + 4 * ah] =                     \
            make_uint4(w0l, w1l, w2l, w3l);                                    \
        h2split(rb0.x, rb1.x, w0h, w0l); h2split(rb0.y, rb1.y, w1h, w1l);      \
        h2split(rb0.z, rb1.z, w2h, w2l); h2split(rb0.w, rb1.w, w3h, w3l);      \
        *(uint4*)&Bh[(buf) * GB_SZ + bp * GB_W + bc] =                         \
            make_uint4(w0h, w1h, w2h, w3h);                                    \
        *(uint4*)&Bl[(buf) * GB_SZ + bp * GB_W + bc] =                         \
            make_uint4(w0l, w1l, w2l, w3l);                                    \
    }

    GEMM_STAGE(0);

    int cur = 0;
    for (int k0 = 0; k0 < K; k0 += 16) {
        __syncthreads();
        const bool more = (k0 + 16) < K;
        if (more) {
            ra0 = *(const float4*)&A[(size_t)(m0 + am) * K + k0 + 16 + 8 * ah];
            ra1 = *(const float4*)&A[(size_t)(m0 + am) * K + k0 + 16 + 8 * ah + 4];
            rb0 = *(const float4*)&B[(size_t)(k0 + 16 + 2 * bp) * LDB + n0 + bc];
            rb1 = *(const float4*)&B[(size_t)(k0 + 16 + 2 * bp + 1) * LDB + n0 + bc];
        }

        const uint32_t* cAh = Ah + cur * GA_SZ;
        const uint32_t* cAl = Al + cur * GA_SZ;
        const uint32_t* cBh = Bh + cur * GB_SZ;
        const uint32_t* cBl = Bl + cur * GB_SZ;

        uint32_t fah[2][4], fal[2][4];
#pragma unroll
        for (int mi = 0; mi < 2; mi++) {
            int r0 = wm + mi * 16 + g;
            fah[mi][0] = cAh[r0 * GA_W + t];
            fah[mi][1] = cAh[(r0 + 8) * GA_W + t];
            fah[mi][2] = cAh[r0 * GA_W + 4 + t];
            fah[mi][3] = cAh[(r0 + 8) * GA_W + 4 + t];
            fal[mi][0] = cAl[r0 * GA_W + t];
            fal[mi][1] = cAl[(r0 + 8) * GA_W + t];
            fal[mi][2] = cAl[r0 * GA_W + 4 + t];
            fal[mi][3] = cAl[(r0 + 8) * GA_W + 4 + t];
        }
#pragma unroll
        for (int jj = 0; jj < 8; jj++) {
            int nn = wn + jj * 8 + g;
            uint32_t bh[2], bl[2];
            bh[0] = cBh[t * GB_W + nn];
            bh[1] = cBh[(4 + t) * GB_W + nn];
            bl[0] = cBl[t * GB_W + nn];
            bl[1] = cBl[(4 + t) * GB_W + nn];
#pragma unroll
            for (int mi = 0; mi < 2; mi++) {
                mma16(c[mi][jj], fah[mi], bh);
                mma16(c[mi][jj], fal[mi], bh);
                mma16(c[mi][jj], fah[mi], bl);
            }
        }

        if (more) GEMM_STAGE(cur ^ 1);
        cur ^= 1;
    }

#pragma unroll
    for (int mi = 0; mi < 2; mi++)
#pragma unroll
        for (int jj = 0; jj < 8; jj++)
#pragma unroll
            for (int e = 0; e < 4; e++) {
                int row = m0 + wm + mi * 16 + g + ((e >= 2) ? 8 : 0);
                int col = n0 + wn + jj * 8 + 2 * t + (e & 1);
                float v = c[mi][jj][e] + bias[col];
                if (QKV) {
                    int bb = row >> 11;
                    int s  = row & (SEQ - 1);
                    int h  = col / 192;
                    int w  = col - h * 192;
                    size_t base = ((size_t)(bb * NHEAD + h) * SEQ + s) * HDIM;
                    if (w < 64)       g_Q[base + w]         = v;
                    else if (w < 128) g_K[base + (w - 64)]  = v;
                    else              g_V[base + (w - 128)] = v;
                } else {
                    outp[(size_t)row * DMODEL + col] = v;
                }
            }
}

__global__ __launch_bounds__(256, 2) void qkv_kernel(const float* __restrict__ X,
                                                     const float* __restrict__ W,
                                                     const float* __restrict__ bias) {
    gemm_body<D3, true>(X, W, bias, nullptr, blockIdx.y * 128, blockIdx.x * 128, DMODEL);
}
__global__ __launch_bounds__(256, 2) void proj_kernel(const float* __restrict__ Wo,
                                                      const float* __restrict__ bo,
                                                      float* __restrict__ out) {
    gemm_body<DMODEL, false>(g_vals, Wo, bo, out, blockIdx.y * 128, blockIdx.x * 128, DMODEL);
}

// ---------------------------------------------------------------------------
// Flash attention: double-buffered K/V (ONE sync per tile), copy staging from
// pre-split planes, P@V 2-term (V hi-plane only).
// ---------------------------------------------------------------------------
#define AQ_W 36
#define AK_W 36
#define AV_W 72
#define KBUF 2304   // 64 * AK_W
#define VBUF 2304   // 32 * AV_W
// Qh | Ql | Kh[2] | Kl[2] | Vh[2]
#define ATTN_WORDS (2 * 128 * AQ_W + 4 * KBUF + 2 * VBUF)
#define ATTN_BYTES (ATTN_WORDS * 4)

__global__ __launch_bounds__(256, 2) void attn_kernel(const float* __restrict__ mask) {
    extern __shared__ uint32_t smw[];
    uint32_t* Qh = smw;                     // 4608
    uint32_t* Ql = Qh + 128 * AQ_W;         // 4608
    uint32_t* Khb = Ql + 128 * AQ_W;        // 2 x 2304
    uint32_t* Klb = Khb + 2 * KBUF;         // 2 x 2304
    uint32_t* Vhb = Klb + 2 * KBUF;         // 2 x 2304

    const int tid = threadIdx.x, lane = tid & 31, w = tid >> 5;
    const int g = lane >> 2, t = lane & 3;
    const int b = blockIdx.z, h = blockIdx.y;
    const int q0 = blockIdx.x * 128;
    const int qrow = w * 16 + g;

    const float* Qg = g_Q + (size_t)(b * NHEAD + h) * SEQ * HDIM;
    const size_t krow0 = (size_t)(b * NHEAD + h) * SEQ;
    const size_t vrow0 = (size_t)(b * NHEAD + h) * (SEQ / 2);
    const float* Mg = mask + (size_t)b * SEQ * SEQ;

    // ---- stage Q once (split in-kernel)
    {
        int m = tid >> 1, hf = tid & 1;
#pragma unroll
        for (int j = 0; j < 4; j++) {
            float4 a = *(const float4*)&Qg[(size_t)(q0 + m) * HDIM + 32 * hf + 8 * j];
            float4 c = *(const float4*)&Qg[(size_t)(q0 + m) * HDIM + 32 * hf + 8 * j + 4];
            uint32_t w0h, w0l, w1h, w1l, w2h, w2l, w3h, w3l;
            h2split(a.x, a.y, w0h, w0l); h2split(a.z, a.w, w1h, w1l);
            h2split(c.x, c.y, w2h, w2l); h2split(c.z, c.w, w3h, w3l);
            *(uint4*)&Qh[m * AQ_W + 16 * hf + 4 * j] = make_uint4(w0h, w1h, w2h, w3h);
            *(uint4*)&Ql[m * AQ_W + 16 * hf + 4 * j] = make_uint4(w0l, w1l, w2l, w3l);
        }
    }

    float o[8][4];
#pragma unroll
    for (int jj = 0; jj < 8; jj++)
#pragma unroll
        for (int e = 0; e < 4; e++) o[jj][e] = 0.f;
    float m0r = -1e30f, m1r = -1e30f, l0 = 0.f, l1 = 0.f;

    // staging maps + prefetch of tile 0
    const int kr = tid >> 2, kq = tid & 3;
    const int vp = tid >> 3, vq = tid & 7;
    uint4 rkh[2], rkl[2], rvh[2];
    {
        const uint32_t* sh = &g_Kph[(krow0 + kr) * 32 + 8 * kq];
        const uint32_t* sl = &g_Kpl[(krow0 + kr) * 32 + 8 * kq];
        rkh[0] = *(const uint4*)&sh[0]; rkh[1] = *(const uint4*)&sh[4];
        rkl[0] = *(const uint4*)&sl[0]; rkl[1] = *(const uint4*)&sl[4];
        const uint32_t* vh = &g_Vph[(vrow0 + vp) * 64 + 8 * vq];
        rvh[0] = *(const uint4*)&vh[0]; rvh[1] = *(const uint4*)&vh[4];
    }

    int cur = 0;
    for (int kt = 0; kt < SEQ; kt += 64) {
        // ---- stage tile i into buf cur (safe: readers of buf cur finished
        //      tile i-2 before the single barrier in iteration i-1)
        uint32_t* Kh = Khb + cur * KBUF;
        uint32_t* Kl = Klb + cur * KBUF;
        uint32_t* Vh = Vhb + cur * VBUF;
        *(uint4*)&Kh[kr * AK_W + 8 * kq]     = rkh[0];
        *(uint4*)&Kh[kr * AK_W + 8 * kq + 4] = rkh[1];
        *(uint4*)&Kl[kr * AK_W + 8 * kq]     = rkl[0];
        *(uint4*)&Kl[kr * AK_W + 8 * kq + 4] = rkl[1];
        *(uint4*)&Vh[vp * AV_W + 8 * vq]     = rvh[0];
        *(uint4*)&Vh[vp * AV_W + 8 * vq + 4] = rvh[1];
        __syncthreads();

        // ---- prefetch tile i+1 (overlaps all of tile i's compute)
        if (kt + 64 < SEQ) {
            const uint32_t* sh = &g_Kph[(krow0 + kt + 64 + kr) * 32 + 8 * kq];
            const uint32_t* sl = &g_Kpl[(krow0 + kt + 64 + kr) * 32 + 8 * kq];
            rkh[0] = *(const uint4*)&sh[0]; rkh[1] = *(const uint4*)&sh[4];
            rkl[0] = *(const uint4*)&sl[0]; rkl[1] = *(const uint4*)&sl[4];
            const uint32_t* vh = &g_Vph[(vrow0 + (kt + 64) / 2 + vp) * 64 + 8 * vq];
            rvh[0] = *(const uint4*)&vh[0]; rvh[1] = *(const uint4*)&vh[4];
        }

        // ---- S = Q @ K^T (3-term)
        float s[8][4];
#pragma unroll
        for (int jj = 0; jj < 8; jj++)
#pragma unroll
            for (int e = 0; e < 4; e++) s[jj][e] = 0.f;

#pragma unroll
        for (int c = 0; c < 4; c++) {
            uint32_t fah[4], fal[4];
            fah[0] = Qh[qrow * AQ_W + 8 * c + t];
            fah[1] = Qh[(qrow + 8) * AQ_W + 8 * c + t];
            fah[2] = Qh[qrow * AQ_W + 8 * c + 4 + t];
            fah[3] = Qh[(qrow + 8) * AQ_W + 8 * c + 4 + t];
            fal[0] = Ql[qrow * AQ_W + 8 * c + t];
            fal[1] = Ql[(qrow + 8) * AQ_W + 8 * c + t];
            fal[2] = Ql[qrow * AQ_W + 8 * c + 4 + t];
            fal[3] = Ql[(qrow + 8) * AQ_W + 8 * c + 4 + t];
#pragma unroll
            for (int jj = 0; jj < 8; jj++) {
                int nn = jj * 8 + g;
                uint32_t bh[2], bl[2];
                bh[0] = Kh[nn * AK_W + 8 * c + t];
                bh[1] = Kh[nn * AK_W + 8 * c + 4 + t];
                bl[0] = Kl[nn * AK_W + 8 * c + t];
                bl[1] = Kl[nn * AK_W + 8 * c + 4 + t];
                mma16(s[jj], fah, bh);
                mma16(s[jj], fal, bh);
                mma16(s[jj], fah, bl);
            }
        }

        // ---- softmax update
        float vm0 = -1e30f, vm1 = -1e30f;
#pragma unroll
        for (int jj = 0; jj < 8; jj++) {
            int col = kt + jj * 8 + 2 * t;
            float2 mk0 = *(const float2*)&Mg[(size_t)(q0 + qrow) * SEQ + col];
            float2 mk1 = *(const float2*)&Mg[(size_t)(q0 + qrow + 8) * SEQ + col];
            s[jj][0] = s[jj][0] * 0.125f + mk0.x;
            s[jj][1] = s[jj][1] * 0.125f + mk0.y;
            s[jj][2] = s[jj][2] * 0.125f + mk1.x;
            s[jj][3] = s[jj][3] * 0.125f + mk1.y;
            vm0 = fmaxf(vm0, fmaxf(s[jj][0], s[jj][1]));
            vm1 = fmaxf(vm1, fmaxf(s[jj][2], s[jj][3]));
        }
        vm0 = fmaxf(vm0, __shfl_xor_sync(0xffffffffu, vm0, 1));
        vm0 = fmaxf(vm0, __shfl_xor_sync(0xffffffffu, vm0, 2));
        vm1 = fmaxf(vm1, __shfl_xor_sync(0xffffffffu, vm1, 1));
        vm1 = fmaxf(vm1, __shfl_xor_sync(0xffffffffu, vm1, 2));

        float mn0 = fmaxf(m0r, vm0), mn1 = fmaxf(m1r, vm1);
        float cor0 = __expf(m0r - mn0), cor1 = __expf(m1r - mn1);
        m0r = mn0; m1r = mn1;
        float rs0 = 0.f, rs1 = 0.f;
#pragma unroll
        for (int jj = 0; jj < 8; jj++) {
            s[jj][0] = __expf(s[jj][0] - mn0);
            s[jj][1] = __expf(s[jj][1] - mn0);
            s[jj][2] = __expf(s[jj][2] - mn1);
            s[jj][3] = __expf(s[jj][3] - mn1);
            rs0 += s[jj][0] + s[jj][1];
            rs1 += s[jj][2] + s[jj][3];
        }
        rs0 += __shfl_xor_sync(0xffffffffu, rs0, 1);
        rs0 += __shfl_xor_sync(0xffffffffu, rs0, 2);
        rs1 += __shfl_xor_sync(0xffffffffu, rs1, 1);
        rs1 += __shfl_xor_sync(0xffffffffu, rs1, 2);
        l0 = l0 * cor0 + rs0;
        l1 = l1 * cor1 + rs1;
#pragma unroll
        for (int jj = 0; jj < 8; jj++) {
            o[jj][0] *= cor0; o[jj][1] *= cor0;
            o[jj][2] *= cor1; o[jj][3] *= cor1;
        }

        // ---- O += P @ V (P split in regs; V hi-plane only; 2 MMAs/frag)
#pragma unroll
        for (int c = 0; c < 4; c++) {
            uint32_t ph[4], pl[4];
            h2split(s[2 * c][0],     s[2 * c][1],     ph[0], pl[0]);
            h2split(s[2 * c][2],     s[2 * c][3],     ph[1], pl[1]);
            h2split(s[2 * c + 1][0], s[2 * c + 1][1], ph[2], pl[2]);
            h2split(s[2 * c + 1][2], s[2 * c + 1][3], ph[3], pl[3]);
#pragma unroll
            for (int jj = 0; jj < 8; jj++) {
                int nn = jj * 8 + g;
                uint32_t bh[2];
                bh[0] = Vh[(8 * c + t) * AV_W + nn];
                bh[1] = Vh[(8 * c + 4 + t) * AV_W + nn];
                mma16(o[jj], ph, bh);
                mma16(o[jj], pl, bh);
            }
        }
        cur ^= 1;
    }

    // ---- write vals float
    float inv0 = 1.f / l0, inv1 = 1.f / l1;
#pragma unroll
    for (int jj = 0; jj < 8; jj++) {
        size_t r0a = (size_t)(b * SEQ + q0 + qrow) * DMODEL + h * HDIM + jj * 8 + 2 * t;
        size_t r1a = (size_t)(b * SEQ + q0 + qrow + 8) * DMODEL + h * HDIM + jj * 8 + 2 * t;
        *(float2*)&g_vals[r0a] = make_float2(o[jj][0] * inv0, o[jj][1] * inv0);
        *(float2*)&g_vals[r1a] = make_float2(o[jj][2] * inv1, o[jj][3] * inv1);
    }
}

// ---------------------------------------------------------------------------
extern "C" void kernel_launch(void* const* d_in, const int* in_sizes, int n_in,
                              void* d_out, int out_size) {
    const float* x    = (const float*)d_in[0];
    const float* mask = (const float*)d_in[1];
    const float* Wqkv = (const float*)d_in[2];
    const float* bqkv = (const float*)d_in[3];
    const float* Wo   = (const float*)d_in[4];
    const float* bo   = (const float*)d_in[5];
    float* out = (float*)d_out;

    cudaFuncSetAttribute(qkv_kernel, cudaFuncAttributeMaxDynamicSharedMemorySize,
                         GEMM_BYTES);
    cudaFuncSetAttribute(proj_kernel, cudaFuncAttributeMaxDynamicSharedMemorySize,
                         GEMM_BYTES);
    cudaFuncSetAttribute(attn_kernel, cudaFuncAttributeMaxDynamicSharedMemorySize,
                         ATTN_BYTES);

    dim3 gq(D3 / 128, (BATCH * SEQ) / 128);
    qkv_kernel<<<gq, 256, GEMM_BYTES>>>(x, Wqkv, bqkv);

    split_k_kernel<<<(KQUADS + 255) / 256, 256>>>();
    split_v_kernel<<<(VPAIRS * 16 + 255) / 256, 256>>>();

    dim3 ga(SEQ / 128, NHEAD, BATCH);
    attn_kernel<<<ga, 256, ATTN_BYTES>>>(mask);

    dim3 gp(DMODEL / 128, (BATCH * SEQ) / 128);
    proj_kernel<<<gp, 256, GEMM_BYTES>>>(Wo, bo, out);
}

// round 14
// speedup vs baseline: 1.5662x; 1.5662x over previous
#include <cuda_runtime.h>
#include <cuda_fp16.h>
#include <stdint.h>

#define BATCH  2
#define SEQ    2048
#define DMODEL 1024
#define NHEAD  16
#define HDIM   64
#define D3     3072

// Scratch: Q/V natural [B,H,S,hd] floats; vals [B,S,D] floats.
__device__ __align__(16) float g_Q   [BATCH * NHEAD * SEQ * HDIM];
__device__ __align__(16) float g_V   [BATCH * NHEAD * SEQ * HDIM];
__device__ __align__(16) float g_vals[BATCH * SEQ * DMODEL];
// Pre-split planes (uint32 = half2 word; low half = smaller index):
//  K planes: [B*H*S][32]   pairs along d (hi+lo) — written directly by qkv epilogue
//  V plane : [B*H*S/2][64] pairs along s (hi only; lo term dropped, validated R13)
__device__ __align__(16) uint32_t g_Kph[BATCH * NHEAD * SEQ * 32];
__device__ __align__(16) uint32_t g_Kpl[BATCH * NHEAD * SEQ * 32];
__device__ __align__(16) uint32_t g_Vph[BATCH * NHEAD * (SEQ / 2) * 64];

// ---- fp16 split helpers ----------------------------------------------------
__device__ __forceinline__ void h2split(float a, float b, uint32_t& hi, uint32_t& lo) {
    __half2 h = __floats2half2_rn(a, b);
    float2 f = __half22float2(h);
    __half2 l = __floats2half2_rn(a - f.x, b - f.y);
    hi = *(uint32_t*)&h;
    lo = *(uint32_t*)&l;
}
__device__ __forceinline__ uint32_t h2hi(float a, float b) {
    __half2 h = __floats2half2_rn(a, b);
    return *(uint32_t*)&h;
}
__device__ __forceinline__ void mma16(float* c, const uint32_t* a, const uint32_t* b) {
    asm volatile(
        "mma.sync.aligned.m16n8k16.row.col.f32.f16.f16.f32 "
        "{%0,%1,%2,%3},{%4,%5,%6,%7},{%8,%9},{%0,%1,%2,%3};"
        : "+f"(c[0]), "+f"(c[1]), "+f"(c[2]), "+f"(c[3])
        : "r"(a[0]), "r"(a[1]), "r"(a[2]), "r"(a[3]), "r"(b[0]), "r"(b[1]));
}

// ---------------------------------------------------------------------------
// Prep: V pairs along s (hi plane only). Device globals referenced directly.
// ---------------------------------------------------------------------------
#define VPAIRS (BATCH * NHEAD * SEQ / 2)
__global__ void split_v_kernel() {
    int i = blockIdx.x * blockDim.x + threadIdx.x;   // p*16 + q
    int p = i >> 4, q4 = (i & 15) * 4;
    if (p >= VPAIRS) return;
    float4 a = *(const float4*)&g_V[(size_t)(2 * p) * HDIM + q4];
    float4 b = *(const float4*)&g_V[(size_t)(2 * p + 1) * HDIM + q4];
    size_t o = (size_t)p * HDIM + q4;
    *(uint4*)&g_Vph[o] = make_uint4(h2hi(a.x, b.x), h2hi(a.y, b.y),
                                    h2hi(a.z, b.z), h2hi(a.w, b.w));
}

// ---------------------------------------------------------------------------
// GEMM (R6-proven): C[128x128], BK=16, 8 warps (4M x 2N), warp 32x64.
// fp16 hi/lo planes in smem, double-buffered, split at staging.
// QKV epilogue writes K directly as split planes.
// ---------------------------------------------------------------------------
#define GA_W   12
#define GB_W   136
#define GA_SZ  (128 * GA_W)
#define GB_SZ  (8 * GB_W)
#define GEMM_WORDS (4 * GA_SZ + 4 * GB_SZ)
#define GEMM_BYTES (GEMM_WORDS * 4)

template <int LDB, bool QKV>
__device__ __forceinline__ void gemm_body(const float* __restrict__ A,
                                          const float* __restrict__ B,
                                          const float* __restrict__ bias,
                                          float* __restrict__ outp,
                                          int m0, int n0, int K) {
    extern __shared__ uint32_t smw[];
    uint32_t* Ah = smw;
    uint32_t* Al = Ah + 2 * GA_SZ;
    uint32_t* Bh = Al + 2 * GA_SZ;
    uint32_t* Bl = Bh + 2 * GB_SZ;

    const int tid = threadIdx.x;
    const int lane = tid & 31, warp = tid >> 5;
    const int g = lane >> 2, t = lane & 3;
    const int wm = (warp & 3) * 32, wn = (warp >> 2) * 64;

    float c[2][8][4];
#pragma unroll
    for (int mi = 0; mi < 2; mi++)
#pragma unroll
        for (int jj = 0; jj < 8; jj++)
#pragma unroll
            for (int e = 0; e < 4; e++) c[mi][jj][e] = 0.f;

    const int am = tid >> 1, ah = tid & 1;
    const int bp = tid >> 5, bc = (tid & 31) * 4;

    float4 ra0, ra1, rb0, rb1;
    ra0 = *(const float4*)&A[(size_t)(m0 + am) * K + 8 * ah];
    ra1 = *(const float4*)&A[(size_t)(m0 + am) * K + 8 * ah + 4];
    rb0 = *(const float4*)&B[(size_t)(2 * bp) * LDB + n0 + bc];
    rb1 = *(const float4*)&B[(size_t)(2 * bp + 1) * LDB + n0 + bc];

#define GEMM_STAGE(buf)                                                        \
    {                                                                          \
        uint32_t w0h, w0l, w1h, w1l, w2h, w2l, w3h, w3l;                       \
        h2split(ra0.x, ra0.y, w0h, w0l); h2split(ra0.z, ra0.w, w1h, w1l);      \
        h2split(ra1.x, ra1.y, w2h, w2l); h2split(ra1.z, ra1.w, w3h, w3l);      \
        *(uint4*)&Ah[(buf) * GA_SZ + am * GA_W + 4 * ah] =                     \
            make_uint4(w0h, w1h, w2h, w3h);                                    \
        *(uint4*)&Al[(buf) * GA_SZ + am * GA_W + 4 * ah] =                     \
            make_uint4(w0l, w1l, w2l, w3l);                                    \
        h2split(rb0.x, rb1.x, w0h, w0l); h2split(rb0.y, rb1.y, w1h, w1l);      \
        h2split(rb0.z, rb1.z, w2h, w2l); h2split(rb0.w, rb1.w, w3h, w3l);      \
        *(uint4*)&Bh[(buf) * GB_SZ + bp * GB_W + bc] =                         \
            make_uint4(w0h, w1h, w2h, w3h);                                    \
        *(uint4*)&Bl[(buf) * GB_SZ + bp * GB_W + bc] =                         \
            make_uint4(w0l, w1l, w2l, w3l);                                    \
    }

    GEMM_STAGE(0);

    int cur = 0;
    for (int k0 = 0; k0 < K; k0 += 16) {
        __syncthreads();
        const bool more = (k0 + 16) < K;
        if (more) {
            ra0 = *(const float4*)&A[(size_t)(m0 + am) * K + k0 + 16 + 8 * ah];
            ra1 = *(const float4*)&A[(size_t)(m0 + am) * K + k0 + 16 + 8 * ah + 4];
            rb0 = *(const float4*)&B[(size_t)(k0 + 16 + 2 * bp) * LDB + n0 + bc];
            rb1 = *(const float4*)&B[(size_t)(k0 + 16 + 2 * bp + 1) * LDB + n0 + bc];
        }

        const uint32_t* cAh = Ah + cur * GA_SZ;
        const uint32_t* cAl = Al + cur * GA_SZ;
        const uint32_t* cBh = Bh + cur * GB_SZ;
        const uint32_t* cBl = Bl + cur * GB_SZ;

        uint32_t fah[2][4], fal[2][4];
#pragma unroll
        for (int mi = 0; mi < 2; mi++) {
            int r0 = wm + mi * 16 + g;
            fah[mi][0] = cAh[r0 * GA_W + t];
            fah[mi][1] = cAh[(r0 + 8) * GA_W + t];
            fah[mi][2] = cAh[r0 * GA_W + 4 + t];
            fah[mi][3] = cAh[(r0 + 8) * GA_W + 4 + t];
            fal[mi][0] = cAl[r0 * GA_W + t];
            fal[mi][1] = cAl[(r0 + 8) * GA_W + t];
            fal[mi][2] = cAl[r0 * GA_W + 4 + t];
            fal[mi][3] = cAl[(r0 + 8) * GA_W + 4 + t];
        }
#pragma unroll
        for (int jj = 0; jj < 8; jj++) {
            int nn = wn + jj * 8 + g;
            uint32_t bh[2], bl[2];
            bh[0] = cBh[t * GB_W + nn];
            bh[1] = cBh[(4 + t) * GB_W + nn];
            bl[0] = cBl[t * GB_W + nn];
            bl[1] = cBl[(4 + t) * GB_W + nn];
#pragma unroll
            for (int mi = 0; mi < 2; mi++) {
                mma16(c[mi][jj], fah[mi], bh);
                mma16(c[mi][jj], fal[mi], bh);
                mma16(c[mi][jj], fah[mi], bl);
            }
        }

        if (more) GEMM_STAGE(cur ^ 1);
        cur ^= 1;
    }

#pragma unroll
    for (int mi = 0; mi < 2; mi++)
#pragma unroll
        for (int jj = 0; jj < 8; jj++) {
            int colb = n0 + wn + jj * 8 + 2 * t;
            float b0 = bias[colb], b1 = bias[colb + 1];
#pragma unroll
            for (int half = 0; half < 2; half++) {
                int row = m0 + wm + mi * 16 + g + half * 8;
                float v0 = c[mi][jj][2 * half + 0] + b0;
                float v1 = c[mi][jj][2 * half + 1] + b1;
                if (QKV) {
                    int bb = row >> 11;
                    int s  = row & (SEQ - 1);
                    int h  = colb / 192;
                    int w  = colb - h * 192;
                    size_t slab = (size_t)(bb * NHEAD + h) * SEQ + s;
                    if (w < 64) {
                        size_t base = slab * HDIM + w;
                        g_Q[base] = v0; g_Q[base + 1] = v1;
                    } else if (w < 128) {
                        uint32_t hi, lo; h2split(v0, v1, hi, lo);
                        size_t idx = slab * 32 + ((w - 64) >> 1);
                        g_Kph[idx] = hi; g_Kpl[idx] = lo;
                    } else {
                        size_t base = slab * HDIM + (w - 128);
                        g_V[base] = v0; g_V[base + 1] = v1;
                    }
                } else {
                    *(float2*)&outp[(size_t)row * DMODEL + colb] = make_float2(v0, v1);
                }
            }
        }
}

__global__ __launch_bounds__(256, 2) void qkv_kernel(const float* __restrict__ X,
                                                     const float* __restrict__ W,
                                                     const float* __restrict__ bias) {
    gemm_body<D3, true>(X, W, bias, nullptr, blockIdx.y * 128, blockIdx.x * 128, DMODEL);
}
__global__ __launch_bounds__(256, 2) void proj_kernel(const float* __restrict__ Wo,
                                                      const float* __restrict__ bo,
                                                      float* __restrict__ out) {
    gemm_body<DMODEL, false>(g_vals, Wo, bo, out, blockIdx.y * 128, blockIdx.x * 128, DMODEL);
}

// ---------------------------------------------------------------------------
// Flash attention (R12 structure: single K/V buffer, two barriers per tile):
// copy staging from pre-split planes; P@V 2-term (V hi-plane only).
// ---------------------------------------------------------------------------
#define AQ_W 36
#define AK_W 36
#define AV_W 72
// Qh | Ql | Kh | Kl | Vh
#define ATTN_WORDS (2 * 128 * AQ_W + 2 * 64 * AK_W + 32 * AV_W)
#define ATTN_BYTES (ATTN_WORDS * 4)

__global__ __launch_bounds__(256, 2) void attn_kernel(const float* __restrict__ mask) {
    extern __shared__ uint32_t smw[];
    uint32_t* Qh = smw;
    uint32_t* Ql = Qh + 128 * AQ_W;
    uint32_t* Kh = Ql + 128 * AQ_W;
    uint32_t* Kl = Kh + 64 * AK_W;
    uint32_t* Vh = Kl + 64 * AK_W;

    const int tid = threadIdx.x, lane = tid & 31, w = tid >> 5;
    const int g = lane >> 2, t = lane & 3;
    const int b = blockIdx.z, h = blockIdx.y;
    const int q0 = blockIdx.x * 128;
    const int qrow = w * 16 + g;

    const float* Qg = g_Q + (size_t)(b * NHEAD + h) * SEQ * HDIM;
    const size_t krow0 = (size_t)(b * NHEAD + h) * SEQ;
    const size_t vrow0 = (size_t)(b * NHEAD + h) * (SEQ / 2);
    const float* Mg = mask + (size_t)b * SEQ * SEQ;

    // ---- stage Q once (split in-kernel)
    {
        int m = tid >> 1, hf = tid & 1;
#pragma unroll
        for (int j = 0; j < 4; j++) {
            float4 a = *(const float4*)&Qg[(size_t)(q0 + m) * HDIM + 32 * hf + 8 * j];
            float4 c = *(const float4*)&Qg[(size_t)(q0 + m) * HDIM + 32 * hf + 8 * j + 4];
            uint32_t w0h, w0l, w1h, w1l, w2h, w2l, w3h, w3l;
            h2split(a.x, a.y, w0h, w0l); h2split(a.z, a.w, w1h, w1l);
            h2split(c.x, c.y, w2h, w2l); h2split(c.z, c.w, w3h, w3l);
            *(uint4*)&Qh[m * AQ_W + 16 * hf + 4 * j] = make_uint4(w0h, w1h, w2h, w3h);
            *(uint4*)&Ql[m * AQ_W + 16 * hf + 4 * j] = make_uint4(w0l, w1l, w2l, w3l);
        }
    }

    float o[8][4];
#pragma unroll
    for (int jj = 0; jj < 8; jj++)
#pragma unroll
        for (int e = 0; e < 4; e++) o[jj][e] = 0.f;
    float m0r = -1e30f, m1r = -1e30f, l0 = 0.f, l1 = 0.f;

    const int kr = tid >> 2, kq = tid & 3;
    const int vp = tid >> 3, vq = tid & 7;
    uint4 rkh[2], rkl[2], rvh[2];
    {
        const uint32_t* sh = &g_Kph[(krow0 + kr) * 32 + 8 * kq];
        const uint32_t* sl = &g_Kpl[(krow0 + kr) * 32 + 8 * kq];
        rkh[0] = *(const uint4*)&sh[0]; rkh[1] = *(const uint4*)&sh[4];
        rkl[0] = *(const uint4*)&sl[0]; rkl[1] = *(const uint4*)&sl[4];
        const uint32_t* vh = &g_Vph[(vrow0 + vp) * 64 + 8 * vq];
        rvh[0] = *(const uint4*)&vh[0]; rvh[1] = *(const uint4*)&vh[4];
    }

    for (int kt = 0; kt < SEQ; kt += 64) {
        __syncthreads();
        *(uint4*)&Kh[kr * AK_W + 8 * kq]     = rkh[0];
        *(uint4*)&Kh[kr * AK_W + 8 * kq + 4] = rkh[1];
        *(uint4*)&Kl[kr * AK_W + 8 * kq]     = rkl[0];
        *(uint4*)&Kl[kr * AK_W + 8 * kq + 4] = rkl[1];
        *(uint4*)&Vh[vp * AV_W + 8 * vq]     = rvh[0];
        *(uint4*)&Vh[vp * AV_W + 8 * vq + 4] = rvh[1];
        __syncthreads();

        if (kt + 64 < SEQ) {
            const uint32_t* sh = &g_Kph[(krow0 + kt + 64 + kr) * 32 + 8 * kq];
            const uint32_t* sl = &g_Kpl[(krow0 + kt + 64 + kr) * 32 + 8 * kq];
            rkh[0] = *(const uint4*)&sh[0]; rkh[1] = *(const uint4*)&sh[4];
            rkl[0] = *(const uint4*)&sl[0]; rkl[1] = *(const uint4*)&sl[4];
            const uint32_t* vh = &g_Vph[(vrow0 + (kt + 64) / 2 + vp) * 64 + 8 * vq];
            rvh[0] = *(const uint4*)&vh[0]; rvh[1] = *(const uint4*)&vh[4];
        }

        // ---- S = Q @ K^T (3-term)
        float s[8][4];
#pragma unroll
        for (int jj = 0; jj < 8; jj++)
#pragma unroll
            for (int e = 0; e < 4; e++) s[jj][e] = 0.f;

#pragma unroll
        for (int c = 0; c < 4; c++) {
            uint32_t fah[4], fal[4];
            fah[0] = Qh[qrow * AQ_W + 8 * c + t];
            fah[1] = Qh[(qrow + 8) * AQ_W + 8 * c + t];
            fah[2] = Qh[qrow * AQ_W + 8 * c + 4 + t];
            fah[3] = Qh[(qrow + 8) * AQ_W + 8 * c + 4 + t];
            fal[0] = Ql[qrow * AQ_W + 8 * c + t];
            fal[1] = Ql[(qrow + 8) * AQ_W + 8 * c + t];
            fal[2] = Ql[qrow * AQ_W + 8 * c + 4 + t];
            fal[3] = Ql[(qrow + 8) * AQ_W + 8 * c + 4 + t];
#pragma unroll
            for (int jj = 0; jj < 8; jj++) {
                int nn = jj * 8 + g;
                uint32_t bh[2], bl[2];
                bh[0] = Kh[nn * AK_W + 8 * c + t];
                bh[1] = Kh[nn * AK_W + 8 * c + 4 + t];
                bl[0] = Kl[nn * AK_W + 8 * c + t];
                bl[1] = Kl[nn * AK_W + 8 * c + 4 + t];
                mma16(s[jj], fah, bh);
                mma16(s[jj], fal, bh);
                mma16(s[jj], fah, bl);
            }
        }

        // ---- softmax update
        float vm0 = -1e30f, vm1 = -1e30f;
#pragma unroll
        for (int jj = 0; jj < 8; jj++) {
            int col = kt + jj * 8 + 2 * t;
            float2 mk0 = *(const float2*)&Mg[(size_t)(q0 + qrow) * SEQ + col];
            float2 mk1 = *(const float2*)&Mg[(size_t)(q0 + qrow + 8) * SEQ + col];
            s[jj][0] = s[jj][0] * 0.125f + mk0.x;
            s[jj][1] = s[jj][1] * 0.125f + mk0.y;
            s[jj][2] = s[jj][2] * 0.125f + mk1.x;
            s[jj][3] = s[jj][3] * 0.125f + mk1.y;
            vm0 = fmaxf(vm0, fmaxf(s[jj][0], s[jj][1]));
            vm1 = fmaxf(vm1, fmaxf(s[jj][2], s[jj][3]));
        }
        vm0 = fmaxf(vm0, __shfl_xor_sync(0xffffffffu, vm0, 1));
        vm0 = fmaxf(vm0, __shfl_xor_sync(0xffffffffu, vm0, 2));
        vm1 = fmaxf(vm1, __shfl_xor_sync(0xffffffffu, vm1, 1));
        vm1 = fmaxf(vm1, __shfl_xor_sync(0xffffffffu, vm1, 2));

        float mn0 = fmaxf(m0r, vm0), mn1 = fmaxf(m1r, vm1);
        float cor0 = __expf(m0r - mn0), cor1 = __expf(m1r - mn1);
        m0r = mn0; m1r = mn1;
        float rs0 = 0.f, rs1 = 0.f;
#pragma unroll
        for (int jj = 0; jj < 8; jj++) {
            s[jj][0] = __expf(s[jj][0] - mn0);
            s[jj][1] = __expf(s[jj][1] - mn0);
            s[jj][2] = __expf(s[jj][2] - mn1);
            s[jj][3] = __expf(s[jj][3] - mn1);
            rs0 += s[jj][0] + s[jj][1];
            rs1 += s[jj][2] + s[jj][3];
        }
        rs0 += __shfl_xor_sync(0xffffffffu, rs0, 1);
        rs0 += __shfl_xor_sync(0xffffffffu, rs0, 2);
        rs1 += __shfl_xor_sync(0xffffffffu, rs1, 1);
        rs1 += __shfl_xor_sync(0xffffffffu, rs1, 2);
        l0 = l0 * cor0 + rs0;
        l1 = l1 * cor1 + rs1;
#pragma unroll
        for (int jj = 0; jj < 8; jj++) {
            o[jj][0] *= cor0; o[jj][1] *= cor0;
            o[jj][2] *= cor1; o[jj][3] *= cor1;
        }

        // ---- O += P @ V (P split in regs; V hi-plane only; 2 MMAs/frag)
#pragma unroll
        for (int c = 0; c < 4; c++) {
            uint32_t ph[4], pl[4];
            h2split(s[2 * c][0],     s[2 * c][1],     ph[0], pl[0]);
            h2split(s[2 * c][2],     s[2 * c][3],     ph[1], pl[1]);
            h2split(s[2 * c + 1][0], s[2 * c + 1][1], ph[2], pl[2]);
            h2split(s[2 * c + 1][2], s[2 * c + 1][3], ph[3], pl[3]);
#pragma unroll
            for (int jj = 0; jj < 8; jj++) {
                int nn = jj * 8 + g;
                uint32_t bh[2];
                bh[0] = Vh[(8 * c + t) * AV_W + nn];
                bh[1] = Vh[(8 * c + 4 + t) * AV_W + nn];
                mma16(o[jj], ph, bh);
                mma16(o[jj], pl, bh);
            }
        }
    }

    // ---- write vals float
    float inv0 = 1.f / l0, inv1 = 1.f / l1;
#pragma unroll
    for (int jj = 0; jj < 8; jj++) {
        size_t r0a = (size_t)(b * SEQ + q0 + qrow) * DMODEL + h * HDIM + jj * 8 + 2 * t;
        size_t r1a = (size_t)(b * SEQ + q0 + qrow + 8) * DMODEL + h * HDIM + jj * 8 + 2 * t;
        *(float2*)&g_vals[r0a] = make_float2(o[jj][0] * inv0, o[jj][1] * inv0);
        *(float2*)&g_vals[r1a] = make_float2(o[jj][2] * inv1, o[jj][3] * inv1);
    }
}

// ---------------------------------------------------------------------------
extern "C" void kernel_launch(void* const* d_in, const int* in_sizes, int n_in,
                              void* d_out, int out_size) {
    const float* x    = (const float*)d_in[0];
    const float* mask = (const float*)d_in[1];
    const float* Wqkv = (const float*)d_in[2];
    const float* bqkv = (const float*)d_in[3];
    const float* Wo   = (const float*)d_in[4];
    const float* bo   = (const float*)d_in[5];
    float* out = (float*)d_out;

    cudaFuncSetAttribute(qkv_kernel, cudaFuncAttributeMaxDynamicSharedMemorySize,
                         GEMM_BYTES);
    cudaFuncSetAttribute(proj_kernel, cudaFuncAttributeMaxDynamicSharedMemorySize,
                         GEMM_BYTES);
    cudaFuncSetAttribute(attn_kernel, cudaFuncAttributeMaxDynamicSharedMemorySize,
                         ATTN_BYTES);

    dim3 gq(D3 / 128, (BATCH * SEQ) / 128);
    qkv_kernel<<<gq, 256, GEMM_BYTES>>>(x, Wqkv, bqkv);

    split_v_kernel<<<(VPAIRS * 16 + 255) / 256, 256>>>();

    dim3 ga(SEQ / 128, NHEAD, BATCH);
    attn_kernel<<<ga, 256, ATTN_BYTES>>>(mask);

    dim3 gp(DMODEL / 128, (BATCH * SEQ) / 128);
    proj_kernel<<<gp, 256, GEMM_BYTES>>>(Wo, bo, out);
}

// round 17
// speedup vs baseline: 1.7529x; 1.1192x over previous
#include <cuda_runtime.h>
#include <cuda_fp16.h>
#include <stdint.h>

#define BATCH  2
#define SEQ    2048
#define DMODEL 1024
#define NHEAD  16
#define HDIM   64
#define D3     3072

// Scratch: Q/V natural [B,H,S,hd] floats; vals [B,S,D] floats.
__device__ __align__(16) float g_Q   [BATCH * NHEAD * SEQ * HDIM];
__device__ __align__(16) float g_V   [BATCH * NHEAD * SEQ * HDIM];
__device__ __align__(16) float g_vals[BATCH * SEQ * DMODEL];
// Pre-split planes (uint32 = half2 word; low half = smaller index):
//  K plane: [B*H*S][32]   pairs along d (hi ONLY — K-lo term dropped; Q keeps hi+lo)
//  V plane: [B*H*S/2][64] pairs along s (hi only; validated R13/R14)
__device__ __align__(16) uint32_t g_Kph[BATCH * NHEAD * SEQ * 32];
__device__ __align__(16) uint32_t g_Vph[BATCH * NHEAD * (SEQ / 2) * 64];

// ---- fp16 split helpers ----------------------------------------------------
__device__ __forceinline__ void h2split(float a, float b, uint32_t& hi, uint32_t& lo) {
    __half2 h = __floats2half2_rn(a, b);
    float2 f = __half22float2(h);
    __half2 l = __floats2half2_rn(a - f.x, b - f.y);
    hi = *(uint32_t*)&h;
    lo = *(uint32_t*)&l;
}
__device__ __forceinline__ uint32_t h2hi(float a, float b) {
    __half2 h = __floats2half2_rn(a, b);
    return *(uint32_t*)&h;
}
__device__ __forceinline__ void mma16(float* c, const uint32_t* a, const uint32_t* b) {
    asm volatile(
        "mma.sync.aligned.m16n8k16.row.col.f32.f16.f16.f32 "
        "{%0,%1,%2,%3},{%4,%5,%6,%7},{%8,%9},{%0,%1,%2,%3};"
        : "+f"(c[0]), "+f"(c[1]), "+f"(c[2]), "+f"(c[3])
        : "r"(a[0]), "r"(a[1]), "r"(a[2]), "r"(a[3]), "r"(b[0]), "r"(b[1]));
}

// ---------------------------------------------------------------------------
// Prep: V pairs along s (hi plane only). Device globals referenced directly.
// ---------------------------------------------------------------------------
#define VPAIRS (BATCH * NHEAD * SEQ / 2)
__global__ void split_v_kernel() {
    int i = blockIdx.x * blockDim.x + threadIdx.x;   // p*16 + q
    int p = i >> 4, q4 = (i & 15) * 4;
    if (p >= VPAIRS) return;
    float4 a = *(const float4*)&g_V[(size_t)(2 * p) * HDIM + q4];
    float4 b = *(const float4*)&g_V[(size_t)(2 * p + 1) * HDIM + q4];
    size_t o = (size_t)p * HDIM + q4;
    *(uint4*)&g_Vph[o] = make_uint4(h2hi(a.x, b.x), h2hi(a.y, b.y),
                                    h2hi(a.z, b.z), h2hi(a.w, b.w));
}

// ---------------------------------------------------------------------------
// GEMM: C[128x128], BK=16, 8 warps (4M x 2N), warp 32x64.
// TERMS=3: AhBh + AlBh + AhBl (qkv). TERMS=2: AhBh + AlBh, B-lo plane unused (proj).
// ---------------------------------------------------------------------------
#define GA_W   12
#define GB_W   136
#define GA_SZ  (128 * GA_W)
#define GB_SZ  (8 * GB_W)
#define GEMM_WORDS (4 * GA_SZ + 4 * GB_SZ)
#define GEMM_BYTES (GEMM_WORDS * 4)

template <int LDB, bool QKV, int TERMS>
__device__ __forceinline__ void gemm_body(const float* __restrict__ A,
                                          const float* __restrict__ B,
                                          const float* __restrict__ bias,
                                          float* __restrict__ outp,
                                          int m0, int n0, int K) {
    extern __shared__ uint32_t smw[];
    uint32_t* Ah = smw;
    uint32_t* Al = Ah + 2 * GA_SZ;
    uint32_t* Bh = Al + 2 * GA_SZ;
    uint32_t* Bl = Bh + 2 * GB_SZ;

    const int tid = threadIdx.x;
    const int lane = tid & 31, warp = tid >> 5;
    const int g = lane >> 2, t = lane & 3;
    const int wm = (warp & 3) * 32, wn = (warp >> 2) * 64;

    float c[2][8][4];
#pragma unroll
    for (int mi = 0; mi < 2; mi++)
#pragma unroll
        for (int jj = 0; jj < 8; jj++)
#pragma unroll
            for (int e = 0; e < 4; e++) c[mi][jj][e] = 0.f;

    const int am = tid >> 1, ah = tid & 1;
    const int bp = tid >> 5, bc = (tid & 31) * 4;

    float4 ra0, ra1, rb0, rb1;
    ra0 = *(const float4*)&A[(size_t)(m0 + am) * K + 8 * ah];
    ra1 = *(const float4*)&A[(size_t)(m0 + am) * K + 8 * ah + 4];
    rb0 = *(const float4*)&B[(size_t)(2 * bp) * LDB + n0 + bc];
    rb1 = *(const float4*)&B[(size_t)(2 * bp + 1) * LDB + n0 + bc];

#define GEMM_STAGE(buf)                                                        \
    {                                                                          \
        uint32_t w0h, w0l, w1h, w1l, w2h, w2l, w3h, w3l;                       \
        h2split(ra0.x, ra0.y, w0h, w0l); h2split(ra0.z, ra0.w, w1h, w1l);      \
        h2split(ra1.x, ra1.y, w2h, w2l); h2split(ra1.z, ra1.w, w3h, w3l);      \
        *(uint4*)&Ah[(buf) * GA_SZ + am * GA_W + 4 * ah] =                     \
            make_uint4(w0h, w1h, w2h, w3h);                                    \
        *(uint4*)&Al[(buf) * GA_SZ + am * GA_W + 4 * ah] =                     \
            make_uint4(w0l, w1l, w2l, w3l);                                    \
        if (TERMS == 3) {                                                      \
            h2split(rb0.x, rb1.x, w0h, w0l); h2split(rb0.y, rb1.y, w1h, w1l);  \
            h2split(rb0.z, rb1.z, w2h, w2l); h2split(rb0.w, rb1.w, w3h, w3l);  \
            *(uint4*)&Bh[(buf) * GB_SZ + bp * GB_W + bc] =                     \
                make_uint4(w0h, w1h, w2h, w3h);                                \
            *(uint4*)&Bl[(buf) * GB_SZ + bp * GB_W + bc] =                     \
                make_uint4(w0l, w1l, w2l, w3l);                                \
        } else {                                                               \
            *(uint4*)&Bh[(buf) * GB_SZ + bp * GB_W + bc] =                     \
                make_uint4(h2hi(rb0.x, rb1.x), h2hi(rb0.y, rb1.y),             \
                           h2hi(rb0.z, rb1.z), h2hi(rb0.w, rb1.w));            \
        }                                                                      \
    }

    GEMM_STAGE(0);

    int cur = 0;
    for (int k0 = 0; k0 < K; k0 += 16) {
        __syncthreads();
        const bool more = (k0 + 16) < K;
        if (more) {
            ra0 = *(const float4*)&A[(size_t)(m0 + am) * K + k0 + 16 + 8 * ah];
            ra1 = *(const float4*)&A[(size_t)(m0 + am) * K + k0 + 16 + 8 * ah + 4];
            rb0 = *(const float4*)&B[(size_t)(k0 + 16 + 2 * bp) * LDB + n0 + bc];
            rb1 = *(const float4*)&B[(size_t)(k0 + 16 + 2 * bp + 1) * LDB + n0 + bc];
        }

        const uint32_t* cAh = Ah + cur * GA_SZ;
        const uint32_t* cAl = Al + cur * GA_SZ;
        const uint32_t* cBh = Bh + cur * GB_SZ;
        const uint32_t* cBl = Bl + cur * GB_SZ;

        uint32_t fah[2][4], fal[2][4];
#pragma unroll
        for (int mi = 0; mi < 2; mi++) {
            int r0 = wm + mi * 16 + g;
            fah[mi][0] = cAh[r0 * GA_W + t];
            fah[mi][1] = cAh[(r0 + 8) * GA_W + t];
            fah[mi][2] = cAh[r0 * GA_W + 4 + t];
            fah[mi][3] = cAh[(r0 + 8) * GA_W + 4 + t];
            fal[mi][0] = cAl[r0 * GA_W + t];
            fal[mi][1] = cAl[(r0 + 8) * GA_W + t];
            fal[mi][2] = cAl[r0 * GA_W + 4 + t];
            fal[mi][3] = cAl[(r0 + 8) * GA_W + 4 + t];
        }
#pragma unroll
        for (int jj = 0; jj < 8; jj++) {
            int nn = wn + jj * 8 + g;
            uint32_t bh[2], bl[2];
            bh[0] = cBh[t * GB_W + nn];
            bh[1] = cBh[(4 + t) * GB_W + nn];
            if (TERMS == 3) {
                bl[0] = cBl[t * GB_W + nn];
                bl[1] = cBl[(4 + t) * GB_W + nn];
            }
#pragma unroll
            for (int mi = 0; mi < 2; mi++) {
                mma16(c[mi][jj], fah[mi], bh);
                mma16(c[mi][jj], fal[mi], bh);
                if (TERMS == 3) mma16(c[mi][jj], fah[mi], bl);
            }
        }

        if (more) GEMM_STAGE(cur ^ 1);
        cur ^= 1;
    }

#pragma unroll
    for (int mi = 0; mi < 2; mi++)
#pragma unroll
        for (int jj = 0; jj < 8; jj++) {
            int colb = n0 + wn + jj * 8 + 2 * t;
            float b0 = bias[colb], b1 = bias[colb + 1];
#pragma unroll
            for (int half = 0; half < 2; half++) {
                int row = m0 + wm + mi * 16 + g + half * 8;
                float v0 = c[mi][jj][2 * half + 0] + b0;
                float v1 = c[mi][jj][2 * half + 1] + b1;
                if (QKV) {
                    int bb = row >> 11;
                    int s  = row & (SEQ - 1);
                    int h  = colb / 192;
                    int w  = colb - h * 192;
                    size_t slab = (size_t)(bb * NHEAD + h) * SEQ + s;
                    if (w < 64) {
                        size_t base = slab * HDIM + w;
                        g_Q[base] = v0; g_Q[base + 1] = v1;
                    } else if (w < 128) {
                        g_Kph[slab * 32 + ((w - 64) >> 1)] = h2hi(v0, v1);
                    } else {
                        size_t base = slab * HDIM + (w - 128);
                        g_V[base] = v0; g_V[base + 1] = v1;
                    }
                } else {
                    *(float2*)&outp[(size_t)row * DMODEL + colb] = make_float2(v0, v1);
                }
            }
        }
}

__global__ __launch_bounds__(256, 2) void qkv_kernel(const float* __restrict__ X,
                                                     const float* __restrict__ W,
                                                     const float* __restrict__ bias) {
    gemm_body<D3, true, 3>(X, W, bias, nullptr, blockIdx.y * 128, blockIdx.x * 128, DMODEL);
}
__global__ __launch_bounds__(256, 2) void proj_kernel(const float* __restrict__ Wo,
                                                      const float* __restrict__ bo,
                                                      float* __restrict__ out) {
    gemm_body<DMODEL, false, 2>(g_vals, Wo, bo, out, blockIdx.y * 128, blockIdx.x * 128, DMODEL);
}

// ---------------------------------------------------------------------------
// Flash attention: QK 2-term (K hi-plane only), PV 2-term (V hi-plane only).
// Single K/V buffer, two barriers per tile (R12/R14-proven structure).
// ---------------------------------------------------------------------------
#define AQ_W 36
#define AK_W 36
#define AV_W 72
// Qh | Ql | Kh | Vh
#define ATTN_WORDS (2 * 128 * AQ_W + 64 * AK_W + 32 * AV_W)
#define ATTN_BYTES (ATTN_WORDS * 4)

__global__ __launch_bounds__(256, 2) void attn_kernel(const float* __restrict__ mask) {
    extern __shared__ uint32_t smw[];
    uint32_t* Qh = smw;
    uint32_t* Ql = Qh + 128 * AQ_W;
    uint32_t* Kh = Ql + 128 * AQ_W;
    uint32_t* Vh = Kh + 64 * AK_W;

    const int tid = threadIdx.x, lane = tid & 31, w = tid >> 5;
    const int g = lane >> 2, t = lane & 3;
    const int b = blockIdx.z, h = blockIdx.y;
    const int q0 = blockIdx.x * 128;
    const int qrow = w * 16 + g;

    const float* Qg = g_Q + (size_t)(b * NHEAD + h) * SEQ * HDIM;
    const size_t krow0 = (size_t)(b * NHEAD + h) * SEQ;
    const size_t vrow0 = (size_t)(b * NHEAD + h) * (SEQ / 2);
    const float* Mg = mask + (size_t)b * SEQ * SEQ;

    // ---- stage Q once (split in-kernel; Q keeps hi+lo)
    {
        int m = tid >> 1, hf = tid & 1;
#pragma unroll
        for (int j = 0; j < 4; j++) {
            float4 a = *(const float4*)&Qg[(size_t)(q0 + m) * HDIM + 32 * hf + 8 * j];
            float4 c = *(const float4*)&Qg[(size_t)(q0 + m) * HDIM + 32 * hf + 8 * j + 4];
            uint32_t w0h, w0l, w1h, w1l, w2h, w2l, w3h, w3l;
            h2split(a.x, a.y, w0h, w0l); h2split(a.z, a.w, w1h, w1l);
            h2split(c.x, c.y, w2h, w2l); h2split(c.z, c.w, w3h, w3l);
            *(uint4*)&Qh[m * AQ_W + 16 * hf + 4 * j] = make_uint4(w0h, w1h, w2h, w3h);
            *(uint4*)&Ql[m * AQ_W + 16 * hf + 4 * j] = make_uint4(w0l, w1l, w2l, w3l);
        }
    }

    float o[8][4];
#pragma unroll
    for (int jj = 0; jj < 8; jj++)
#pragma unroll
        for (int e = 0; e < 4; e++) o[jj][e] = 0.f;
    float m0r = -1e30f, m1r = -1e30f, l0 = 0.f, l1 = 0.f;

    const int kr = tid >> 2, kq = tid & 3;
    const int vp = tid >> 3, vq = tid & 7;
    uint4 rkh[2], rvh[2];
    {
        const uint32_t* sh = &g_Kph[(krow0 + kr) * 32 + 8 * kq];
        rkh[0] = *(const uint4*)&sh[0]; rkh[1] = *(const uint4*)&sh[4];
        const uint32_t* vh = &g_Vph[(vrow0 + vp) * 64 + 8 * vq];
        rvh[0] = *(const uint4*)&vh[0]; rvh[1] = *(const uint4*)&vh[4];
    }

    for (int kt = 0; kt < SEQ; kt += 64) {
        __syncthreads();
        *(uint4*)&Kh[kr * AK_W + 8 * kq]     = rkh[0];
        *(uint4*)&Kh[kr * AK_W + 8 * kq + 4] = rkh[1];
        *(uint4*)&Vh[vp * AV_W + 8 * vq]     = rvh[0];
        *(uint4*)&Vh[vp * AV_W + 8 * vq + 4] = rvh[1];
        __syncthreads();

        if (kt + 64 < SEQ) {
            const uint32_t* sh = &g_Kph[(krow0 + kt + 64 + kr) * 32 + 8 * kq];
            rkh[0] = *(const uint4*)&sh[0]; rkh[1] = *(const uint4*)&sh[4];
            const uint32_t* vh = &g_Vph[(vrow0 + (kt + 64) / 2 + vp) * 64 + 8 * vq];
            rvh[0] = *(const uint4*)&vh[0]; rvh[1] = *(const uint4*)&vh[4];
        }

        // ---- S = Q @ K^T (2-term: (Qh+Ql)·Kh)
        float s[8][4];
#pragma unroll
        for (int jj = 0; jj < 8; jj++)
#pragma unroll
            for (int e = 0; e < 4; e++) s[jj][e] = 0.f;

#pragma unroll
        for (int c = 0; c < 4; c++) {
            uint32_t fah[4], fal[4];
            fah[0] = Qh[qrow * AQ_W + 8 * c + t];
            fah[1] = Qh[(qrow + 8) * AQ_W + 8 * c + t];
            fah[2] = Qh[qrow * AQ_W + 8 * c + 4 + t];
            fah[3] = Qh[(qrow + 8) * AQ_W + 8 * c + 4 + t];
            fal[0] = Ql[qrow * AQ_W + 8 * c + t];
            fal[1] = Ql[(qrow + 8) * AQ_W + 8 * c + t];
            fal[2] = Ql[qrow * AQ_W + 8 * c + 4 + t];
            fal[3] = Ql[(qrow + 8) * AQ_W + 8 * c + 4 + t];
#pragma unroll
            for (int jj = 0; jj < 8; jj++) {
                int nn = jj * 8 + g;
                uint32_t bh[2];
                bh[0] = Kh[nn * AK_W + 8 * c + t];
                bh[1] = Kh[nn * AK_W + 8 * c + 4 + t];
                mma16(s[jj], fah, bh);
                mma16(s[jj], fal, bh);
            }
        }

        // ---- softmax update
        float vm0 = -1e30f, vm1 = -1e30f;
#pragma unroll
        for (int jj = 0; jj < 8; jj++) {
            int col = kt + jj * 8 + 2 * t;
            float2 mk0 = *(const float2*)&Mg[(size_t)(q0 + qrow) * SEQ + col];
            float2 mk1 = *(const float2*)&Mg[(size_t)(q0 + qrow + 8) * SEQ + col];
            s[jj][0] = s[jj][0] * 0.125f + mk0.x;
            s[jj][1] = s[jj][1] * 0.125f + mk0.y;
            s[jj][2] = s[jj][2] * 0.125f + mk1.x;
            s[jj][3] = s[jj][3] * 0.125f + mk1.y;
            vm0 = fmaxf(vm0, fmaxf(s[jj][0], s[jj][1]));
            vm1 = fmaxf(vm1, fmaxf(s[jj][2], s[jj][3]));
        }
        vm0 = fmaxf(vm0, __shfl_xor_sync(0xffffffffu, vm0, 1));
        vm0 = fmaxf(vm0, __shfl_xor_sync(0xffffffffu, vm0, 2));
        vm1 = fmaxf(vm1, __shfl_xor_sync(0xffffffffu, vm1, 1));
        vm1 = fmaxf(vm1, __shfl_xor_sync(0xffffffffu, vm1, 2));

        float mn0 = fmaxf(m0r, vm0), mn1 = fmaxf(m1r, vm1);
        float cor0 = __expf(m0r - mn0), cor1 = __expf(m1r - mn1);
        m0r = mn0; m1r = mn1;
        float rs0 = 0.f, rs1 = 0.f;
#pragma unroll
        for (int jj = 0; jj < 8; jj++) {
            s[jj][0] = __expf(s[jj][0] - mn0);
            s[jj][1] = __expf(s[jj][1] - mn0);
            s[jj][2] = __expf(s[jj][2] - mn1);
            s[jj][3] = __expf(s[jj][3] - mn1);
            rs0 += s[jj][0] + s[jj][1];
            rs1 += s[jj][2] + s[jj][3];
        }
        rs0 += __shfl_xor_sync(0xffffffffu, rs0, 1);
        rs0 += __shfl_xor_sync(0xffffffffu, rs0, 2);
        rs1 += __shfl_xor_sync(0xffffffffu, rs1, 1);
        rs1 += __shfl_xor_sync(0xffffffffu, rs1, 2);
        l0 = l0 * cor0 + rs0;
        l1 = l1 * cor1 + rs1;
#pragma unroll
        for (int jj = 0; jj < 8; jj++) {
            o[jj][0] *= cor0; o[jj][1] *= cor0;
            o[jj][2] *= cor1; o[jj][3] *= cor1;
        }

        // ---- O += P @ V (P split in regs; V hi-plane only)
#pragma unroll
        for (int c = 0; c < 4; c++) {
            uint32_t ph[4], pl[4];
            h2split(s[2 * c][0],     s[2 * c][1],     ph[0], pl[0]);
            h2split(s[2 * c][2],     s[2 * c][3],     ph[1], pl[1]);
            h2split(s[2 * c + 1][0], s[2 * c + 1][1], ph[2], pl[2]);
            h2split(s[2 * c + 1][2], s[2 * c + 1][3], ph[3], pl[3]);
#pragma unroll
            for (int jj = 0; jj < 8; jj++) {
                int nn = jj * 8 + g;
                uint32_t bh[2];
                bh[0] = Vh[(8 * c + t) * AV_W + nn];
                bh[1] = Vh[(8 * c + 4 + t) * AV_W + nn];
                mma16(o[jj], ph, bh);
                mma16(o[jj], pl, bh);
            }
        }
    }

    // ---- write vals float
    float inv0 = 1.f / l0, inv1 = 1.f / l1;
#pragma unroll
    for (int jj = 0; jj < 8; jj++) {
        size_t r0a = (size_t)(b * SEQ + q0 + qrow) * DMODEL + h * HDIM + jj * 8 + 2 * t;
        size_t r1a = (size_t)(b * SEQ + q0 + qrow + 8) * DMODEL + h * HDIM + jj * 8 + 2 * t;
        *(float2*)&g_vals[r0a] = make_float2(o[jj][0] * inv0, o[jj][1] * inv0);
        *(float2*)&g_vals[r1a] = make_float2(o[jj][2] * inv1, o[jj][3] * inv1);
    }
}

// ---------------------------------------------------------------------------
extern "C" void kernel_launch(void* const* d_in, const int* in_sizes, int n_in,
                              void* d_out, int out_size) {
    const float* x    = (const float*)d_in[0];
    const float* mask = (const float*)d_in[1];
    const float* Wqkv = (const float*)d_in[2];
    const float* bqkv = (const float*)d_in[3];
    const float* Wo   = (const float*)d_in[4];
    const float* bo   = (const float*)d_in[5];
    float* out = (float*)d_out;

    cudaFuncSetAttribute(qkv_kernel, cudaFuncAttributeMaxDynamicSharedMemorySize,
                         GEMM_BYTES);
    cudaFuncSetAttribute(proj_kernel, cudaFuncAttributeMaxDynamicSharedMemorySize,
                         GEMM_BYTES);
    cudaFuncSetAttribute(attn_kernel, cudaFuncAttributeMaxDynamicSharedMemorySize,
                         ATTN_BYTES);

    dim3 gq(D3 / 128, (BATCH * SEQ) / 128);
    qkv_kernel<<<gq, 256, GEMM_BYTES>>>(x, Wqkv, bqkv);

    split_v_kernel<<<(VPAIRS * 16 + 255) / 256, 256>>>();

    dim3 ga(SEQ / 128, NHEAD, BATCH);
    attn_kernel<<<ga, 256, ATTN_BYTES>>>(mask);

    dim3 gp(DMODEL / 128, (BATCH * SEQ) / 128);
    proj_kernel<<<gp, 256, GEMM_BYTES>>>(Wo, bo, out);
}